// round 4
// baseline (speedup 1.0000x reference)
#include <cuda_runtime.h>

#define Bsz 4
#define Nn 300
#define TOP 36
#define Cc 2048
#define Dd 2048
#define NROI (Bsz*TOP)

// ---------------- scratch (device globals, no allocation) ----------------
__device__ int   g_valid[NROI];
__device__ int   g_level[NROI];
__device__ int   g_dest[NROI];
__device__ int   g_ny[NROI], g_nx[NROI];
__device__ int   g_yi[NROI][28], g_xi[NROI][28];
__device__ float g_yw[NROI][28], g_xw[NROI][28];
__device__ float g_pooled[NROI][Cc];
__device__ int   g_order[NROI];
__device__ int   g_n0;

#define KSPLIT 8
__device__ float g_part[KSPLIT][NROI][Dd];

__device__ __forceinline__ int level_size(int l) {
    return (l == 0) ? 100 : (l == 1) ? 50 : (l == 2) ? 25 : 13;
}

// Streaming separable axis table: 14 monotone samples -> merged (idx, weight)
// list (<=28 entries). Exactly replicates reference bilinear accumulation.
__device__ int build_axis(float start, float rlen, int Hs, int* gidx, float* gwt) {
    int   li[28];
    float lw[28];
    int n = 0;
    float step7  = rlen / 7.0f;
    float step14 = rlen / 14.0f;
    for (int i = 0; i < 14; i++) {
        float yy = start + (float)(i >> 1) * step7 + ((float)(i & 1) + 0.5f) * step14;
        if (yy < -1.0f || yy > (float)Hs) continue;
        float yc = fminf(fmaxf(yy, 0.0f), (float)Hs - 1.0f);
        int i0 = (int)floorf(yc);
        int i1 = min(i0 + 1, Hs - 1);
        float w = yc - (float)i0;
        float w0 = 1.0f - w;
        if (n > 0 && li[n-1] == i0)      lw[n-1] += w0;
        else if (n > 1 && li[n-2] == i0) lw[n-2] += w0;
        else { li[n] = i0; lw[n] = w0; n++; }
        if (n > 0 && li[n-1] == i1)      lw[n-1] += w;
        else if (n > 1 && li[n-2] == i1) lw[n-2] += w;
        else { li[n] = i1; lw[n] = w; n++; }
    }
    for (int t = 0; t < n; t++) { gidx[t] = li[t]; gwt[t] = lw[t]; }
    return n;
}

// ---------------- kernel 1: filter + sort + warp NMS + tables + dest ----------------
__global__ void select_kernel(const float* __restrict__ boxes,
                              const float* __restrict__ scores) {
    int b = blockIdx.x;
    int tid = threadIdx.x;
    __shared__ float ss[Nn];
    __shared__ float sx1[Nn], sy1[Nn], sx2[Nn], sy2[Nn];
    __shared__ int   s_selidx[TOP];
    __shared__ int   s_cnt;
    __shared__ int   s_M;
    __shared__ int   keys[TOP];

    const float* sc = scores + b * Nn;
    const float* bx = boxes + (size_t)b * Nn * 4;

    if (tid == 0) s_M = 0;
    for (int i = tid; i < Nn; i += blockDim.x) ss[i] = sc[i];
    __syncthreads();

    // parallel count of confidence-passing boxes
    {
        int local = 0;
        for (int i = tid; i < Nn; i += blockDim.x) local += (ss[i] > 0.3f);
        #pragma unroll
        for (int o = 16; o; o >>= 1) local += __shfl_down_sync(0xffffffffu, local, o);
        if ((tid & 31) == 0 && local) atomicAdd(&s_M, local);
    }

    // rank-scatter sort of the confidence-filtered subset only
    for (int i = tid; i < Nn; i += blockDim.x) {
        float si = ss[i];
        if (si > 0.3f) {
            int rank = 0;
            for (int j = 0; j < Nn; j++) {
                float sj = ss[j];
                rank += (sj > 0.3f) && ((sj > si) || (sj == si && j < i));
            }
            sx1[rank] = bx[i * 4 + 0];
            sy1[rank] = bx[i * 4 + 1];
            sx2[rank] = bx[i * 4 + 2];
            sy2[rank] = bx[i * 4 + 3];
        }
    }
    __syncthreads();

    int M = s_M;

    // warp-synchronous greedy NMS on warp 0, register keep-bitmasks, no barriers
    if (tid < 32) {
        int lane = tid;
        unsigned kmask = 0;
        #pragma unroll
        for (int s2 = 0; s2 < 10; s2++)
            if (lane + 32 * s2 < M) kmask |= (1u << s2);
        int cnt = 0;
        for (int i = 0; i < M; i++) {
            unsigned om = __shfl_sync(0xffffffffu, kmask, i & 31);
            if (!((om >> (i >> 5)) & 1u)) continue;
            if (lane == 0) s_selidx[cnt] = i;
            cnt++;
            if (cnt >= TOP) break;
            float x1 = sx1[i], y1 = sy1[i], x2 = sx2[i], y2 = sy2[i];
            float ai = (x2 - x1) * (y2 - y1);
            #pragma unroll
            for (int s2 = 0; s2 < 10; s2++) {
                int j = lane + 32 * s2;
                if (((kmask >> s2) & 1u) && j > i && j < M) {
                    float jx1 = sx1[j], jy1 = sy1[j], jx2 = sx2[j], jy2 = sy2[j];
                    float xx1 = fmaxf(x1, jx1);
                    float yy1 = fmaxf(y1, jy1);
                    float xx2 = fminf(x2, jx2);
                    float yy2 = fminf(y2, jy2);
                    float inter = fmaxf(xx2 - xx1, 0.0f) * fmaxf(yy2 - yy1, 0.0f);
                    float aj = (jx2 - jx1) * (jy2 - jy1);
                    float iou = inter / (ai + aj - inter);
                    if (iou > 0.7f) kmask &= ~(1u << s2);
                }
            }
        }
        if (lane == 0) s_cnt = cnt;
    }
    __syncthreads();

    if (tid < TOP) {
        int r = tid;
        int roi = b * TOP + r;
        int valid = 0, lvl = 0;
        if (r < s_cnt) {
            valid = 1;
            int i = s_selidx[r];
            float bx0 = sx1[i], bx1 = sy1[i], bx2 = sx2[i], bx3 = sy2[i];
            float dx = bx2 - bx0, dy = bx3 - bx1;
            float diag = sqrtf(dx * dx + dy * dy);
            float lf = floorf(4.0f + log2f(diag / 224.0f * 4.0f));
            lf = fminf(fmaxf(lf, 2.0f), 5.0f);
            lvl = (int)lf - 2;
            int Hs = level_size(lvl);
            float rw = fmaxf(bx2 - bx0, 1.0f);
            float rh = fmaxf(bx3 - bx1, 1.0f);
            g_ny[roi] = build_axis(bx1, rh, Hs, g_yi[roi], g_yw[roi]);
            g_nx[roi] = build_axis(bx0, rw, Hs, g_xi[roi], g_xw[roi]);
        } else {
            g_ny[roi] = 0;
            g_nx[roi] = 0;
        }
        g_valid[roi] = valid;
        g_level[roi] = lvl;
        keys[r] = valid ? (lvl * TOP + r) : (4 * TOP + r);
    }
    __syncthreads();
    if (tid < TOP) {
        int k = keys[tid];
        int d = 0;
        for (int q = 0; q < TOP; q++) d += (keys[q] < k);
        g_dest[b * TOP + tid] = d;
    }
}

// ---------------- kernel 1b: roi scheduling (class/level/image grouping) ----------------
// class 0 = valid level-0 rois (streaming feat0), class 1 = everything else
// (levels 1-3: L2-resident working set; invalid rois just write zeros).
__global__ void schedule_kernel() {
    __shared__ int keys[NROI];
    int t = threadIdx.x;
    if (t < NROI) {
        int lvl = g_level[t];
        int img = t / TOP;
        int cls = (g_valid[t] && lvl == 0) ? 0 : 1;
        keys[t] = cls * 4096 + lvl * 8 + img;
    }
    __syncthreads();
    if (t < NROI) {
        int k = keys[t];
        int rank = 0;
        for (int j = 0; j < NROI; j++)
            rank += (keys[j] < k) || (keys[j] == k && j < t);
        g_order[rank] = t;
    }
    if (t == 0) {
        int n0 = 0;
        for (int j = 0; j < NROI; j++) n0 += (keys[j] < 4096);
        g_n0 = n0;
    }
}

// ---------------- kernel 2: ROI pooling (two phases) ----------------
// grid: (NROI, 16), block: 256 threads (8 warps x 16 channels each).
__global__ void pool_kernel(const float* __restrict__ f0, const float* __restrict__ f1,
                            const float* __restrict__ f2, const float* __restrict__ f3,
                            int phase) {
    int slot = blockIdx.x;
    int n0 = g_n0;
    if (phase == 0 ? (slot >= n0) : (slot < n0)) return;
    int roi  = g_order[slot];
    int cblk = blockIdx.y;
    int tid  = threadIdx.x;

    if (!g_valid[roi]) {
        if (tid < 128) g_pooled[roi][cblk * 128 + tid] = 0.0f;
        return;
    }

    __shared__ int   soff[784];
    __shared__ float swt[784];

    int lvl = g_level[roi];
    int Hs  = level_size(lvl);
    int HW  = Hs * Hs;
    const float* fm = (lvl == 0) ? f0 : (lvl == 1) ? f1 : (lvl == 2) ? f2 : f3;

    int ny = g_ny[roi], nx = g_nx[roi];
    int n = ny * nx;
    for (int k = tid; k < n; k += 256) {
        int a = k / nx;
        int q = k - a * nx;
        soff[k] = g_yi[roi][a] * Hs + g_xi[roi][q];
        swt[k]  = g_yw[roi][a] * g_xw[roi][q];
    }
    __syncthreads();

    int bimg = roi / TOP;
    int warp = tid >> 5, lane = tid & 31;
    for (int cc = warp; cc < 128; cc += 8) {
        int c = cblk * 128 + cc;
        const float* base = fm + ((size_t)(bimg * Cc + c)) * (size_t)HW;
        float s0 = 0.0f, s1 = 0.0f, s2 = 0.0f, s3 = 0.0f;
        int k = lane;
        for (; k + 96 < n; k += 128) {
            s0 += base[soff[k     ]] * swt[k     ];
            s1 += base[soff[k + 32]] * swt[k + 32];
            s2 += base[soff[k + 64]] * swt[k + 64];
            s3 += base[soff[k + 96]] * swt[k + 96];
        }
        for (; k < n; k += 32)
            s0 += base[soff[k]] * swt[k];
        float sum = (s0 + s1) + (s2 + s3);
        #pragma unroll
        for (int o = 16; o; o >>= 1)
            sum += __shfl_down_sync(0xffffffffu, sum, o);
        if (lane == 0)
            g_pooled[roi][c] = sum * (1.0f / 196.0f);
    }
}

// ---------------- kernel 3: split-K=8 GEMM with packed f32x2 FMA ----------------
#define BM 48
#define BN 64
#define BK 32
#define KSEG (Cc / KSPLIT)   // 256

__global__ void gemm_kernel(const float* __restrict__ Wm) {
    __shared__ float As[BK][BM];
    __shared__ float Bs[BK][BN + 2];

    int m0 = blockIdx.y * BM;
    int n0 = blockIdx.x * BN;
    int ks = blockIdx.z;
    int kbase = ks * KSEG;

    int tid = threadIdx.x;          // 128 threads
    int ti = tid & 15;              // 16 m-groups of 3
    int tj = tid >> 4;              // 8  n-groups of 8

    unsigned long long acc2[3][4] = {};

    for (int k0 = 0; k0 < KSEG; k0 += BK) {
        #pragma unroll
        for (int q = 0; q < 12; q++) {
            int e = tid + q * 128;
            int m = e >> 5, k = e & 31;
            As[k][m] = g_pooled[m0 + m][kbase + k0 + k];
        }
        #pragma unroll
        for (int q = 0; q < 16; q++) {
            int e = tid + q * 128;
            int nn = e >> 5, k = e & 31;
            Bs[k][nn] = Wm[(size_t)(n0 + nn) * Cc + kbase + k0 + k];
        }
        __syncthreads();
        #pragma unroll 8
        for (int kk = 0; kk < BK; kk++) {
            unsigned long long b2[4];
            #pragma unroll
            for (int v = 0; v < 4; v++)
                b2[v] = *reinterpret_cast<const unsigned long long*>(&Bs[kk][tj * 8 + 2 * v]);
            #pragma unroll
            for (int u = 0; u < 3; u++) {
                unsigned au = __float_as_uint(As[kk][ti * 3 + u]);
                unsigned long long a2;
                asm("mov.b64 %0, {%1, %1};" : "=l"(a2) : "r"(au));
                #pragma unroll
                for (int v = 0; v < 4; v++)
                    asm("fma.rn.f32x2 %0, %1, %2, %0;" : "+l"(acc2[u][v]) : "l"(a2), "l"(b2[v]));
            }
        }
        __syncthreads();
    }

    #pragma unroll
    for (int u = 0; u < 3; u++) {
        int m = m0 + ti * 3 + u;
        float* prow = &g_part[ks][m][n0 + tj * 8];
        #pragma unroll
        for (int v = 0; v < 4; v++) {
            *reinterpret_cast<unsigned long long*>(&prow[2 * v]) = acc2[u][v];
        }
    }
}

// ---------------- kernel 4: combine partials + bias + mask + permute ----------------
__global__ void combine_kernel(const float* __restrict__ bias,
                               float* __restrict__ out) {
    int m = blockIdx.x;                         // 144
    int n = blockIdx.y * 256 + threadIdx.x;     // 2048
    int bimg = m / TOP;
    float v = 0.0f;
    if (g_valid[m]) {
        v = bias[n];
        #pragma unroll
        for (int s = 0; s < KSPLIT; s++)
            v += g_part[s][m][n];
    }
    out[((size_t)(bimg * TOP + g_dest[m])) * Dd + n] = v;
}

// ---------------- launch ----------------
extern "C" void kernel_launch(void* const* d_in, const int* in_sizes, int n_in,
                              void* d_out, int out_size) {
    const float* boxes  = (const float*)d_in[0];
    const float* scores = (const float*)d_in[1];
    const float* f0     = (const float*)d_in[2];
    const float* f1     = (const float*)d_in[3];
    const float* f2     = (const float*)d_in[4];
    const float* f3     = (const float*)d_in[5];
    const float* Wm     = (const float*)d_in[6];
    const float* bias   = (const float*)d_in[7];
    float* out = (float*)d_out;

    select_kernel<<<Bsz, 128>>>(boxes, scores);
    schedule_kernel<<<1, 160>>>();
    pool_kernel<<<dim3(NROI, 16), 256>>>(f0, f1, f2, f3, 0);  // level-0 rois (stream feat0)
    pool_kernel<<<dim3(NROI, 16), 256>>>(f0, f1, f2, f3, 1);  // levels 1-3 (L2-resident)
    gemm_kernel<<<dim3(Dd / BN, NROI / BM, KSPLIT), 128>>>(Wm);
    combine_kernel<<<dim3(NROI, Dd / 256), 256>>>(bias, out);
}

// round 5
// speedup vs baseline: 1.3808x; 1.3808x over previous
#include <cuda_runtime.h>

#define Bsz 4
#define Nn 300
#define TOP 36
#define Cc 2048
#define Dd 2048
#define NROI (Bsz*TOP)

// ---------------- scratch (device globals, no allocation) ----------------
__device__ int   g_valid[NROI];
__device__ int   g_level[NROI];
__device__ int   g_dest[NROI];
__device__ int   g_ny[NROI], g_nx[NROI];
__device__ int   g_yi[NROI][28], g_xi[NROI][28];
__device__ float g_yw[NROI][28], g_xw[NROI][28];
__device__ float g_pooled[NROI][Cc];
__device__ int   g_order[NROI];

#define KSPLIT 8
__device__ float g_part[KSPLIT][NROI][Dd];

__device__ __forceinline__ int level_size(int l) {
    return (l == 0) ? 100 : (l == 1) ? 50 : (l == 2) ? 25 : 13;
}

// Streaming separable axis table: 14 monotone samples -> merged (idx, weight)
// list (<=28 entries). Exactly replicates reference bilinear accumulation.
__device__ int build_axis(float start, float rlen, int Hs, int* gidx, float* gwt) {
    int   li[28];
    float lw[28];
    int n = 0;
    float step7  = rlen / 7.0f;
    float step14 = rlen / 14.0f;
    for (int i = 0; i < 14; i++) {
        float yy = start + (float)(i >> 1) * step7 + ((float)(i & 1) + 0.5f) * step14;
        if (yy < -1.0f || yy > (float)Hs) continue;
        float yc = fminf(fmaxf(yy, 0.0f), (float)Hs - 1.0f);
        int i0 = (int)floorf(yc);
        int i1 = min(i0 + 1, Hs - 1);
        float w = yc - (float)i0;
        float w0 = 1.0f - w;
        if (n > 0 && li[n-1] == i0)      lw[n-1] += w0;
        else if (n > 1 && li[n-2] == i0) lw[n-2] += w0;
        else { li[n] = i0; lw[n] = w0; n++; }
        if (n > 0 && li[n-1] == i1)      lw[n-1] += w;
        else if (n > 1 && li[n-2] == i1) lw[n-2] += w;
        else { li[n] = i1; lw[n] = w; n++; }
    }
    for (int t = 0; t < n; t++) { gidx[t] = li[t]; gwt[t] = lw[t]; }
    return n;
}

// ---------------- kernel 1: filter + sort + warp NMS + tables + dest ----------------
__global__ void select_kernel(const float* __restrict__ boxes,
                              const float* __restrict__ scores) {
    int b = blockIdx.x;
    int tid = threadIdx.x;
    __shared__ float ss[Nn];
    __shared__ float sx1[Nn], sy1[Nn], sx2[Nn], sy2[Nn];
    __shared__ int   s_selidx[TOP];
    __shared__ int   s_cnt;
    __shared__ int   s_M;
    __shared__ int   keys[TOP];

    const float* sc = scores + b * Nn;
    const float* bx = boxes + (size_t)b * Nn * 4;

    if (tid == 0) s_M = 0;
    for (int i = tid; i < Nn; i += blockDim.x) ss[i] = sc[i];
    __syncthreads();

    // parallel count of confidence-passing boxes
    {
        int local = 0;
        for (int i = tid; i < Nn; i += blockDim.x) local += (ss[i] > 0.3f);
        #pragma unroll
        for (int o = 16; o; o >>= 1) local += __shfl_down_sync(0xffffffffu, local, o);
        if ((tid & 31) == 0 && local) atomicAdd(&s_M, local);
    }

    // rank-scatter sort of the confidence-filtered subset only
    for (int i = tid; i < Nn; i += blockDim.x) {
        float si = ss[i];
        if (si > 0.3f) {
            int rank = 0;
            for (int j = 0; j < Nn; j++) {
                float sj = ss[j];
                rank += (sj > 0.3f) && ((sj > si) || (sj == si && j < i));
            }
            sx1[rank] = bx[i * 4 + 0];
            sy1[rank] = bx[i * 4 + 1];
            sx2[rank] = bx[i * 4 + 2];
            sy2[rank] = bx[i * 4 + 3];
        }
    }
    __syncthreads();

    int M = s_M;

    // warp-synchronous greedy NMS on warp 0, register keep-bitmasks, no barriers
    if (tid < 32) {
        int lane = tid;
        unsigned kmask = 0;
        #pragma unroll
        for (int s2 = 0; s2 < 10; s2++)
            if (lane + 32 * s2 < M) kmask |= (1u << s2);
        int cnt = 0;
        for (int i = 0; i < M; i++) {
            unsigned om = __shfl_sync(0xffffffffu, kmask, i & 31);
            if (!((om >> (i >> 5)) & 1u)) continue;
            if (lane == 0) s_selidx[cnt] = i;
            cnt++;
            if (cnt >= TOP) break;
            float x1 = sx1[i], y1 = sy1[i], x2 = sx2[i], y2 = sy2[i];
            float ai = (x2 - x1) * (y2 - y1);
            #pragma unroll
            for (int s2 = 0; s2 < 10; s2++) {
                int j = lane + 32 * s2;
                if (((kmask >> s2) & 1u) && j > i && j < M) {
                    float jx1 = sx1[j], jy1 = sy1[j], jx2 = sx2[j], jy2 = sy2[j];
                    float xx1 = fmaxf(x1, jx1);
                    float yy1 = fmaxf(y1, jy1);
                    float xx2 = fminf(x2, jx2);
                    float yy2 = fminf(y2, jy2);
                    float inter = fmaxf(xx2 - xx1, 0.0f) * fmaxf(yy2 - yy1, 0.0f);
                    float aj = (jx2 - jx1) * (jy2 - jy1);
                    float iou = inter / (ai + aj - inter);
                    if (iou > 0.7f) kmask &= ~(1u << s2);
                }
            }
        }
        if (lane == 0) s_cnt = cnt;
    }
    __syncthreads();

    if (tid < TOP) {
        int r = tid;
        int roi = b * TOP + r;
        int valid = 0, lvl = 0;
        if (r < s_cnt) {
            valid = 1;
            int i = s_selidx[r];
            float bx0 = sx1[i], bx1 = sy1[i], bx2 = sx2[i], bx3 = sy2[i];
            float dx = bx2 - bx0, dy = bx3 - bx1;
            float diag = sqrtf(dx * dx + dy * dy);
            float lf = floorf(4.0f + log2f(diag / 224.0f * 4.0f));
            lf = fminf(fmaxf(lf, 2.0f), 5.0f);
            lvl = (int)lf - 2;
            int Hs = level_size(lvl);
            float rw = fmaxf(bx2 - bx0, 1.0f);
            float rh = fmaxf(bx3 - bx1, 1.0f);
            g_ny[roi] = build_axis(bx1, rh, Hs, g_yi[roi], g_yw[roi]);
            g_nx[roi] = build_axis(bx0, rw, Hs, g_xi[roi], g_xw[roi]);
        } else {
            g_ny[roi] = 0;
            g_nx[roi] = 0;
        }
        g_valid[roi] = valid;
        g_level[roi] = lvl;
        keys[r] = valid ? (lvl * TOP + r) : (4 * TOP + r);
    }
    __syncthreads();
    if (tid < TOP) {
        int k = keys[tid];
        int d = 0;
        for (int q = 0; q < TOP; q++) d += (keys[q] < k);
        g_dest[b * TOP + tid] = d;
    }
}

// ---------------- kernel 1b: LPT ordering (slow level-0 rois first) ----------------
__global__ void schedule_kernel() {
    __shared__ int keys[NROI];
    int t = threadIdx.x;
    if (t < NROI) {
        int lvl = g_level[t];
        int img = t / TOP;
        // valid rois ordered by (level asc, image), invalid last
        keys[t] = g_valid[t] ? (lvl * 8 + img) : 1024;
    }
    __syncthreads();
    if (t < NROI) {
        int k = keys[t];
        int rank = 0;
        for (int j = 0; j < NROI; j++)
            rank += (keys[j] < k) || (keys[j] == k && j < t);
        g_order[rank] = t;
    }
}

// ---------------- kernel 2: ROI pooling ----------------
// grid: (NROI, 32), block: 256 threads. 64 channels per block,
// each warp: 8 channels as 4 pairs with shared tap loads (MLP 4).
__global__ void pool_kernel(const float* __restrict__ f0, const float* __restrict__ f1,
                            const float* __restrict__ f2, const float* __restrict__ f3) {
    int roi  = g_order[blockIdx.x];
    int cblk = blockIdx.y;
    int tid  = threadIdx.x;

    if (!g_valid[roi]) {
        if (tid < 64) g_pooled[roi][cblk * 64 + tid] = 0.0f;
        return;
    }

    __shared__ int   soff[784];
    __shared__ float swt[784];

    int lvl = g_level[roi];
    int Hs  = level_size(lvl);
    int HW  = Hs * Hs;
    const float* fm = (lvl == 0) ? f0 : (lvl == 1) ? f1 : (lvl == 2) ? f2 : f3;

    int ny = g_ny[roi], nx = g_nx[roi];
    int n = ny * nx;
    for (int k = tid; k < n; k += 256) {
        int a = k / nx;
        int q = k - a * nx;
        soff[k] = g_yi[roi][a] * Hs + g_xi[roi][q];
        swt[k]  = g_yw[roi][a] * g_xw[roi][q];
    }
    __syncthreads();

    int bimg = roi / TOP;
    int warp = tid >> 5, lane = tid & 31;
    #pragma unroll
    for (int p = 0; p < 4; p++) {
        int c = cblk * 64 + (warp << 3) + (p << 1);
        const float* b0 = fm + ((size_t)(bimg * Cc + c)) * (size_t)HW;
        const float* b1 = b0 + HW;
        float a00 = 0.0f, a01 = 0.0f, a10 = 0.0f, a11 = 0.0f;
        int k = lane;
        for (; k + 32 < n; k += 64) {
            int   o0 = soff[k],      o1 = soff[k + 32];
            float w0 = swt[k],       w1 = swt[k + 32];
            float v00 = b0[o0], v01 = b0[o1], v10 = b1[o0], v11 = b1[o1];
            a00 += v00 * w0;  a01 += v01 * w1;
            a10 += v10 * w0;  a11 += v11 * w1;
        }
        if (k < n) {
            int o = soff[k]; float w = swt[k];
            a00 += b0[o] * w;
            a10 += b1[o] * w;
        }
        float s0 = a00 + a01;
        float s1 = a10 + a11;
        #pragma unroll
        for (int o = 16; o; o >>= 1) {
            s0 += __shfl_down_sync(0xffffffffu, s0, o);
            s1 += __shfl_down_sync(0xffffffffu, s1, o);
        }
        if (lane == 0) {
            g_pooled[roi][c]     = s0 * (1.0f / 196.0f);
            g_pooled[roi][c + 1] = s1 * (1.0f / 196.0f);
        }
    }
}

// ---------------- kernel 3: split-K=8 GEMM with packed f32x2 FMA ----------------
#define BM 48
#define BN 64
#define BK 32
#define KSEG (Cc / KSPLIT)   // 256

__global__ void gemm_kernel(const float* __restrict__ Wm) {
    __shared__ float As[BK][BM];
    __shared__ float Bs[BK][BN + 2];

    int m0 = blockIdx.y * BM;
    int n0 = blockIdx.x * BN;
    int ks = blockIdx.z;
    int kbase = ks * KSEG;

    int tid = threadIdx.x;          // 128 threads
    int ti = tid & 15;              // 16 m-groups of 3
    int tj = tid >> 4;              // 8  n-groups of 8

    unsigned long long acc2[3][4] = {};

    for (int k0 = 0; k0 < KSEG; k0 += BK) {
        #pragma unroll
        for (int q = 0; q < 12; q++) {
            int e = tid + q * 128;
            int m = e >> 5, k = e & 31;
            As[k][m] = g_pooled[m0 + m][kbase + k0 + k];
        }
        #pragma unroll
        for (int q = 0; q < 16; q++) {
            int e = tid + q * 128;
            int nn = e >> 5, k = e & 31;
            Bs[k][nn] = Wm[(size_t)(n0 + nn) * Cc + kbase + k0 + k];
        }
        __syncthreads();
        #pragma unroll 8
        for (int kk = 0; kk < BK; kk++) {
            unsigned long long b2[4];
            #pragma unroll
            for (int v = 0; v < 4; v++)
                b2[v] = *reinterpret_cast<const unsigned long long*>(&Bs[kk][tj * 8 + 2 * v]);
            #pragma unroll
            for (int u = 0; u < 3; u++) {
                unsigned au = __float_as_uint(As[kk][ti * 3 + u]);
                unsigned long long a2;
                asm("mov.b64 %0, {%1, %1};" : "=l"(a2) : "r"(au));
                #pragma unroll
                for (int v = 0; v < 4; v++)
                    asm("fma.rn.f32x2 %0, %1, %2, %0;" : "+l"(acc2[u][v]) : "l"(a2), "l"(b2[v]));
            }
        }
        __syncthreads();
    }

    #pragma unroll
    for (int u = 0; u < 3; u++) {
        int m = m0 + ti * 3 + u;
        float* prow = &g_part[ks][m][n0 + tj * 8];
        #pragma unroll
        for (int v = 0; v < 4; v++) {
            *reinterpret_cast<unsigned long long*>(&prow[2 * v]) = acc2[u][v];
        }
    }
}

// ---------------- kernel 4: combine partials + bias + mask + permute ----------------
__global__ void combine_kernel(const float* __restrict__ bias,
                               float* __restrict__ out) {
    int m = blockIdx.x;                         // 144
    int n = blockIdx.y * 256 + threadIdx.x;     // 2048
    int bimg = m / TOP;
    float v = 0.0f;
    if (g_valid[m]) {
        v = bias[n];
        #pragma unroll
        for (int s = 0; s < KSPLIT; s++)
            v += g_part[s][m][n];
    }
    out[((size_t)(bimg * TOP + g_dest[m])) * Dd + n] = v;
}

// ---------------- launch ----------------
extern "C" void kernel_launch(void* const* d_in, const int* in_sizes, int n_in,
                              void* d_out, int out_size) {
    const float* boxes  = (const float*)d_in[0];
    const float* scores = (const float*)d_in[1];
    const float* f0     = (const float*)d_in[2];
    const float* f1     = (const float*)d_in[3];
    const float* f2     = (const float*)d_in[4];
    const float* f3     = (const float*)d_in[5];
    const float* Wm     = (const float*)d_in[6];
    const float* bias   = (const float*)d_in[7];
    float* out = (float*)d_out;

    select_kernel<<<Bsz, 128>>>(boxes, scores);
    schedule_kernel<<<1, 160>>>();
    pool_kernel<<<dim3(NROI, 32), 256>>>(f0, f1, f2, f3);
    gemm_kernel<<<dim3(Dd / BN, NROI / BM, KSPLIT), 128>>>(Wm);
    combine_kernel<<<dim3(NROI, Dd / 256), 256>>>(bias, out);
}

// round 6
// speedup vs baseline: 1.4905x; 1.0794x over previous
#include <cuda_runtime.h>

#define Bsz 4
#define Nn 300
#define TOP 36
#define Cc 2048
#define Dd 2048
#define NROI (Bsz*TOP)

// ---------------- scratch (device globals, no allocation) ----------------
__device__ int   g_valid[NROI];
__device__ int   g_level[NROI];
__device__ int   g_dest[NROI];
__device__ int   g_ny[NROI], g_nx[NROI];
__device__ int   g_yi[NROI][28], g_xi[NROI][28];
__device__ float g_yw[NROI][28], g_xw[NROI][28];
__device__ float g_pooled[NROI][Cc];
__device__ int   g_order[NROI];

#define KSPLIT 16
__device__ float g_part[KSPLIT][NROI][Dd];

__device__ __forceinline__ int level_size(int l) {
    return (l == 0) ? 100 : (l == 1) ? 50 : (l == 2) ? 25 : 13;
}

// Streaming separable axis table: 14 monotone samples -> merged (idx, weight)
// list (<=28 entries). Exactly replicates reference bilinear accumulation.
__device__ int build_axis(float start, float rlen, int Hs, int* gidx, float* gwt) {
    int   li[28];
    float lw[28];
    int n = 0;
    float step7  = rlen / 7.0f;
    float step14 = rlen / 14.0f;
    for (int i = 0; i < 14; i++) {
        float yy = start + (float)(i >> 1) * step7 + ((float)(i & 1) + 0.5f) * step14;
        if (yy < -1.0f || yy > (float)Hs) continue;
        float yc = fminf(fmaxf(yy, 0.0f), (float)Hs - 1.0f);
        int i0 = (int)floorf(yc);
        int i1 = min(i0 + 1, Hs - 1);
        float w = yc - (float)i0;
        float w0 = 1.0f - w;
        if (n > 0 && li[n-1] == i0)      lw[n-1] += w0;
        else if (n > 1 && li[n-2] == i0) lw[n-2] += w0;
        else { li[n] = i0; lw[n] = w0; n++; }
        if (n > 0 && li[n-1] == i1)      lw[n-1] += w;
        else if (n > 1 && li[n-2] == i1) lw[n-2] += w;
        else { li[n] = i1; lw[n] = w; n++; }
    }
    for (int t = 0; t < n; t++) { gidx[t] = li[t]; gwt[t] = lw[t]; }
    return n;
}

// ---------------- kernel 1: filter + sort + warp NMS + tables + dest ----------------
__global__ void select_kernel(const float* __restrict__ boxes,
                              const float* __restrict__ scores) {
    int b = blockIdx.x;
    int tid = threadIdx.x;
    __shared__ float ss[Nn];
    __shared__ float sx1[Nn], sy1[Nn], sx2[Nn], sy2[Nn];
    __shared__ int   s_selidx[TOP];
    __shared__ int   s_cnt;
    __shared__ int   s_M;
    __shared__ int   keys[TOP];

    const float* sc = scores + b * Nn;
    const float* bx = boxes + (size_t)b * Nn * 4;

    if (tid == 0) s_M = 0;
    for (int i = tid; i < Nn; i += blockDim.x) ss[i] = sc[i];
    __syncthreads();

    {
        int local = 0;
        for (int i = tid; i < Nn; i += blockDim.x) local += (ss[i] > 0.3f);
        #pragma unroll
        for (int o = 16; o; o >>= 1) local += __shfl_down_sync(0xffffffffu, local, o);
        if ((tid & 31) == 0 && local) atomicAdd(&s_M, local);
    }

    for (int i = tid; i < Nn; i += blockDim.x) {
        float si = ss[i];
        if (si > 0.3f) {
            int rank = 0;
            for (int j = 0; j < Nn; j++) {
                float sj = ss[j];
                rank += (sj > 0.3f) && ((sj > si) || (sj == si && j < i));
            }
            sx1[rank] = bx[i * 4 + 0];
            sy1[rank] = bx[i * 4 + 1];
            sx2[rank] = bx[i * 4 + 2];
            sy2[rank] = bx[i * 4 + 3];
        }
    }
    __syncthreads();

    int M = s_M;

    if (tid < 32) {
        int lane = tid;
        unsigned kmask = 0;
        #pragma unroll
        for (int s2 = 0; s2 < 10; s2++)
            if (lane + 32 * s2 < M) kmask |= (1u << s2);
        int cnt = 0;
        for (int i = 0; i < M; i++) {
            unsigned om = __shfl_sync(0xffffffffu, kmask, i & 31);
            if (!((om >> (i >> 5)) & 1u)) continue;
            if (lane == 0) s_selidx[cnt] = i;
            cnt++;
            if (cnt >= TOP) break;
            float x1 = sx1[i], y1 = sy1[i], x2 = sx2[i], y2 = sy2[i];
            float ai = (x2 - x1) * (y2 - y1);
            #pragma unroll
            for (int s2 = 0; s2 < 10; s2++) {
                int j = lane + 32 * s2;
                if (((kmask >> s2) & 1u) && j > i && j < M) {
                    float jx1 = sx1[j], jy1 = sy1[j], jx2 = sx2[j], jy2 = sy2[j];
                    float xx1 = fmaxf(x1, jx1);
                    float yy1 = fmaxf(y1, jy1);
                    float xx2 = fminf(x2, jx2);
                    float yy2 = fminf(y2, jy2);
                    float inter = fmaxf(xx2 - xx1, 0.0f) * fmaxf(yy2 - yy1, 0.0f);
                    float aj = (jx2 - jx1) * (jy2 - jy1);
                    float iou = inter / (ai + aj - inter);
                    if (iou > 0.7f) kmask &= ~(1u << s2);
                }
            }
        }
        if (lane == 0) s_cnt = cnt;
    }
    __syncthreads();

    if (tid < TOP) {
        int r = tid;
        int roi = b * TOP + r;
        int valid = 0, lvl = 0;
        if (r < s_cnt) {
            valid = 1;
            int i = s_selidx[r];
            float bx0 = sx1[i], bx1 = sy1[i], bx2 = sx2[i], bx3 = sy2[i];
            float dx = bx2 - bx0, dy = bx3 - bx1;
            float diag = sqrtf(dx * dx + dy * dy);
            float lf = floorf(4.0f + log2f(diag / 224.0f * 4.0f));
            lf = fminf(fmaxf(lf, 2.0f), 5.0f);
            lvl = (int)lf - 2;
            int Hs = level_size(lvl);
            float rw = fmaxf(bx2 - bx0, 1.0f);
            float rh = fmaxf(bx3 - bx1, 1.0f);
            g_ny[roi] = build_axis(bx1, rh, Hs, g_yi[roi], g_yw[roi]);
            g_nx[roi] = build_axis(bx0, rw, Hs, g_xi[roi], g_xw[roi]);
        } else {
            g_ny[roi] = 0;
            g_nx[roi] = 0;
        }
        g_valid[roi] = valid;
        g_level[roi] = lvl;
        keys[r] = valid ? (lvl * TOP + r) : (4 * TOP + r);
    }
    __syncthreads();
    if (tid < TOP) {
        int k = keys[tid];
        int d = 0;
        for (int q = 0; q < TOP; q++) d += (keys[q] < k);
        g_dest[b * TOP + tid] = d;
    }
}

// ---------------- kernel 1b: LPT ordering (slow level-0 rois first) ----------------
__global__ void schedule_kernel() {
    __shared__ int keys[NROI];
    int t = threadIdx.x;
    if (t < NROI) {
        int lvl = g_level[t];
        int img = t / TOP;
        keys[t] = g_valid[t] ? (lvl * 8 + img) : 1024;
    }
    __syncthreads();
    if (t < NROI) {
        int k = keys[t];
        int rank = 0;
        for (int j = 0; j < NROI; j++)
            rank += (keys[j] < k) || (keys[j] == k && j < t);
        g_order[rank] = t;
    }
}

// ---------------- kernel 2: ROI pooling ----------------
// grid: (NROI, 32), block: 256 threads. 64 channels per block.
// Each warp: 8 channels as 2 quads; per iter 4 planes x 2 taps = 8 LDGs in flight.
__global__ void pool_kernel(const float* __restrict__ f0, const float* __restrict__ f1,
                            const float* __restrict__ f2, const float* __restrict__ f3) {
    int roi  = g_order[blockIdx.x];
    int cblk = blockIdx.y;
    int tid  = threadIdx.x;

    if (!g_valid[roi]) {
        if (tid < 64) g_pooled[roi][cblk * 64 + tid] = 0.0f;
        return;
    }

    __shared__ int   soff[784];
    __shared__ float swt[784];

    int lvl = g_level[roi];
    int Hs  = level_size(lvl);
    int HW  = Hs * Hs;
    const float* fm = (lvl == 0) ? f0 : (lvl == 1) ? f1 : (lvl == 2) ? f2 : f3;

    int ny = g_ny[roi], nx = g_nx[roi];
    int n = ny * nx;
    for (int k = tid; k < n; k += 256) {
        int a = k / nx;
        int q = k - a * nx;
        soff[k] = g_yi[roi][a] * Hs + g_xi[roi][q];
        swt[k]  = g_yw[roi][a] * g_xw[roi][q];
    }
    __syncthreads();

    int bimg = roi / TOP;
    int warp = tid >> 5, lane = tid & 31;
    #pragma unroll
    for (int q = 0; q < 2; q++) {
        int c = cblk * 64 + (warp << 3) + (q << 2);
        const float* b0 = fm + ((size_t)(bimg * Cc + c)) * (size_t)HW;
        const float* b1 = b0 + HW;
        const float* b2 = b1 + HW;
        const float* b3 = b2 + HW;
        float a0 = 0.f, a1 = 0.f, a2 = 0.f, a3 = 0.f;
        float a4 = 0.f, a5 = 0.f, a6 = 0.f, a7 = 0.f;
        int k = lane;
        for (; k + 32 < n; k += 64) {
            int   o0 = soff[k],  o1 = soff[k + 32];
            float w0 = swt[k],   w1 = swt[k + 32];
            float v0 = b0[o0], v1 = b1[o0], v2 = b2[o0], v3 = b3[o0];
            float v4 = b0[o1], v5 = b1[o1], v6 = b2[o1], v7 = b3[o1];
            a0 += v0 * w0;  a1 += v1 * w0;  a2 += v2 * w0;  a3 += v3 * w0;
            a4 += v4 * w1;  a5 += v5 * w1;  a6 += v6 * w1;  a7 += v7 * w1;
        }
        if (k < n) {
            int o = soff[k]; float w = swt[k];
            a0 += b0[o] * w;  a1 += b1[o] * w;
            a2 += b2[o] * w;  a3 += b3[o] * w;
        }
        float s0 = a0 + a4, s1 = a1 + a5, s2 = a2 + a6, s3 = a3 + a7;
        #pragma unroll
        for (int o = 16; o; o >>= 1) {
            s0 += __shfl_down_sync(0xffffffffu, s0, o);
            s1 += __shfl_down_sync(0xffffffffu, s1, o);
            s2 += __shfl_down_sync(0xffffffffu, s2, o);
            s3 += __shfl_down_sync(0xffffffffu, s3, o);
        }
        if (lane == 0) {
            g_pooled[roi][c]     = s0 * (1.0f / 196.0f);
            g_pooled[roi][c + 1] = s1 * (1.0f / 196.0f);
            g_pooled[roi][c + 2] = s2 * (1.0f / 196.0f);
            g_pooled[roi][c + 3] = s3 * (1.0f / 196.0f);
        }
    }
}

// ---------------- kernel 3: split-K=16 GEMM, 6x16 thread tile, f32x2 FMA ----------------
#define BM 48
#define BN 256
#define BK 16
#define KSEG (Cc / KSPLIT)   // 128

__global__ void gemm_kernel(const float* __restrict__ Wm) {
    __shared__ float As[BK][BM];
    __shared__ float Bs[BK][BN + 4];

    int m0 = blockIdx.y * BM;
    int n0 = blockIdx.x * BN;
    int ks = blockIdx.z;
    int kbase = ks * KSEG;

    int tid = threadIdx.x;          // 128
    int ti = tid & 7;               // 8 m-groups of 6
    int tj = tid >> 3;              // 16 n-groups of 16

    unsigned long long acc2[6][8] = {};

    for (int k0 = 0; k0 < KSEG; k0 += BK) {
        // load A tile: 48x16 = 768 floats, 6 per thread
        #pragma unroll
        for (int q = 0; q < 6; q++) {
            int e = tid + q * 128;
            int m = e >> 4, k = e & 15;
            As[k][m] = g_pooled[m0 + m][kbase + k0 + k];
        }
        // load B tile: 16 k x 256 n; thread handles nn = 2*tid, 2*tid+1, float4 over k
        #pragma unroll
        for (int r = 0; r < 2; r++) {
            int nn = 2 * tid + r;
            const float4* src = reinterpret_cast<const float4*>(
                Wm + (size_t)(n0 + nn) * Cc + kbase + k0);
            #pragma unroll
            for (int j = 0; j < 4; j++) {
                float4 v = src[j];
                Bs[4 * j + 0][nn] = v.x;
                Bs[4 * j + 1][nn] = v.y;
                Bs[4 * j + 2][nn] = v.z;
                Bs[4 * j + 3][nn] = v.w;
            }
        }
        __syncthreads();
        #pragma unroll
        for (int kk = 0; kk < BK; kk++) {
            unsigned long long bb[8];
            const float* brow = &Bs[kk][tj * 16];
            #pragma unroll
            for (int v = 0; v < 4; v++) {
                float4 bv = *reinterpret_cast<const float4*>(brow + 4 * v);
                asm("mov.b64 %0, {%1, %2};" : "=l"(bb[2*v])   : "f"(bv.x), "f"(bv.y));
                asm("mov.b64 %0, {%1, %2};" : "=l"(bb[2*v+1]) : "f"(bv.z), "f"(bv.w));
            }
            const float* arow = &As[kk][ti * 6];
            #pragma unroll
            for (int u = 0; u < 6; u++) {
                float av = arow[u];
                unsigned long long ad;
                asm("mov.b64 %0, {%1, %1};" : "=l"(ad) : "f"(av));
                #pragma unroll
                for (int v = 0; v < 8; v++)
                    asm("fma.rn.f32x2 %0, %1, %2, %0;" : "+l"(acc2[u][v]) : "l"(ad), "l"(bb[v]));
            }
        }
        __syncthreads();
    }

    #pragma unroll
    for (int u = 0; u < 6; u++) {
        int m = m0 + ti * 6 + u;
        float* prow = &g_part[ks][m][n0 + tj * 16];
        #pragma unroll
        for (int v = 0; v < 8; v++)
            *reinterpret_cast<unsigned long long*>(&prow[2 * v]) = acc2[u][v];
    }
}

// ---------------- kernel 4: combine partials + bias + mask + permute ----------------
__global__ void combine_kernel(const float* __restrict__ bias,
                               float* __restrict__ out) {
    int m = blockIdx.x;                         // 144
    int n = blockIdx.y * 256 + threadIdx.x;     // 2048
    int bimg = m / TOP;
    float v = 0.0f;
    if (g_valid[m]) {
        v = bias[n];
        #pragma unroll
        for (int s = 0; s < KSPLIT; s++)
            v += g_part[s][m][n];
    }
    out[((size_t)(bimg * TOP + g_dest[m])) * Dd + n] = v;
}

// ---------------- launch ----------------
extern "C" void kernel_launch(void* const* d_in, const int* in_sizes, int n_in,
                              void* d_out, int out_size) {
    const float* boxes  = (const float*)d_in[0];
    const float* scores = (const float*)d_in[1];
    const float* f0     = (const float*)d_in[2];
    const float* f1     = (const float*)d_in[3];
    const float* f2     = (const float*)d_in[4];
    const float* f3     = (const float*)d_in[5];
    const float* Wm     = (const float*)d_in[6];
    const float* bias   = (const float*)d_in[7];
    float* out = (float*)d_out;

    select_kernel<<<Bsz, 128>>>(boxes, scores);
    schedule_kernel<<<1, 160>>>();
    pool_kernel<<<dim3(NROI, 32), 256>>>(f0, f1, f2, f3);
    gemm_kernel<<<dim3(Dd / BN, NROI / BM, KSPLIT), 128>>>(Wm);
    combine_kernel<<<dim3(NROI, Dd / 256), 256>>>(bias, out);
}